// round 10
// baseline (speedup 1.0000x reference)
#include <cuda_runtime.h>
#include <cuda_bf16.h>
#include <math.h>

// Fixed problem shapes
#define B_  1024
#define T_  256
#define C_  64
#define F_  904      // 3*256 + 129 + 7
#define K_  5
#define FC_ (F_ * C_)

// Scratch (device globals: allocation-free contract)
__device__ float  g_xT[B_ * C_ * T_];          // x transposed to [b][c][t]
__device__ float2 g_W4[C_ * 4 * 20 * 32];      // bin-PAIR weights (w_t, w_t4): [c][jp][q][lane]
__device__ float  g_part[C_ * B_ * K_];        // per-(c,b) partial dot products

// ---------------------------------------------------------------------------
// Packed f32x2 helpers (sm_100a).
// ---------------------------------------------------------------------------
__device__ __forceinline__ float2 f2add(float2 a, float2 b) {
    unsigned long long ua = *reinterpret_cast<unsigned long long*>(&a);
    unsigned long long ub = *reinterpret_cast<unsigned long long*>(&b);
    unsigned long long ud;
    asm("add.rn.f32x2 %0, %1, %2;" : "=l"(ud) : "l"(ua), "l"(ub));
    return *reinterpret_cast<float2*>(&ud);
}
__device__ __forceinline__ float2 f2mul(float2 a, float2 b) {
    unsigned long long ua = *reinterpret_cast<unsigned long long*>(&a);
    unsigned long long ub = *reinterpret_cast<unsigned long long*>(&b);
    unsigned long long ud;
    asm("mul.rn.f32x2 %0, %1, %2;" : "=l"(ud) : "l"(ua), "l"(ub));
    return *reinterpret_cast<float2*>(&ud);
}
__device__ __forceinline__ float2 f2fma(float2 a, float2 b, float2 c) {
    unsigned long long ua = *reinterpret_cast<unsigned long long*>(&a);
    unsigned long long ub = *reinterpret_cast<unsigned long long*>(&b);
    unsigned long long uc = *reinterpret_cast<unsigned long long*>(&c);
    unsigned long long ud;
    asm("fma.rn.f32x2 %0, %1, %2, %3;" : "=l"(ud) : "l"(ua), "l"(ub), "l"(uc));
    return *reinterpret_cast<float2*>(&ud);
}
// exact a-b via fma(b, (-1,-1), a)
#define F2SUB(a, b) f2fma((b), NEG1, (a))

// ---------------------------------------------------------------------------
// Weight row value for feature row r, bin t, class k, channel c.
// ---------------------------------------------------------------------------
__device__ __forceinline__ float wval(const float* __restrict__ W,
                                      int r, int t, int k, int c) {
    float w = 0.0f;
    if (r == 0)      w = W[k * FC_ + t * C_ + c];
    else if (r == 1) w = W[k * FC_ + (257 + t) * C_ + c];
    else if (r == 2) w = W[k * FC_ + (513 + t) * C_ + c];
    else {
        const float sc = 1.0f / 24576.0f;   // 1/(fs*sum(win^2))
        if (t == 0)        w = W[k * FC_ + 773 * C_ + c] * sc;
        else if (t < 128)  w = W[k * FC_ + (773 + t) * C_ + c] * (2.0f * sc);
        else if (t == 128) w = W[k * FC_ + (773 + 128) * C_ + c] * sc;
    }
    return w;
}

// ---------------------------------------------------------------------------
// Kernel 1: build bin-pair weight table. Registers j=2*jp, 2*jp+1 hold bins
// t and t+4 (br3 pairs). Element = (w(t), w(t+4)).
// Layout index = ((c*4+jp)*20+q)*32 + lane.
// ---------------------------------------------------------------------------
__global__ void buildW4(const float* __restrict__ W) {
    int idx = blockIdx.x * blockDim.x + threadIdx.x;
    const int N = C_ * 4 * 20 * 32;
    if (idx >= N) return;
    int l  = idx & 31;
    int r1 = idx >> 5;
    int q  = r1 % 20; r1 /= 20;
    int jp = r1 & 3;
    int c  = r1 >> 2;
    const int br3[8] = {0, 4, 2, 6, 1, 5, 3, 7};
    int t = br3[2 * jp] + 8 * (int)(__brev((unsigned)l) >> 27);
    int r = q / 5, k = q - 5 * r;
    g_W4[idx] = make_float2(wval(W, r, t, k, c), wval(W, r, t + 4, k, c));
}

// ---------------------------------------------------------------------------
// Kernel 2: transpose x (B,T,C) -> xT (B,C,T)
// ---------------------------------------------------------------------------
__global__ void transposeX(const float* __restrict__ x) {
    __shared__ float tile[32][33];
    int b  = blockIdx.z;
    int t0 = blockIdx.x * 32;
    int c0 = blockIdx.y * 32;
    int tx = threadIdx.x, ty = threadIdx.y;   // (32,8)
    #pragma unroll
    for (int i = 0; i < 32; i += 8) {
        int t = t0 + ty + i, c = c0 + tx;
        tile[ty + i][tx] = x[(b * T_ + t) * C_ + c];
    }
    __syncthreads();
    #pragma unroll
    for (int i = 0; i < 32; i += 8) {
        int c = c0 + ty + i, t = t0 + tx;
        g_xT[(b * C_ + c) * T_ + t] = tile[tx][ty + i];
    }
}

// ---------------------------------------------------------------------------
// Warp reduction helpers
// ---------------------------------------------------------------------------
__device__ __forceinline__ float wsum(float v) {
    #pragma unroll
    for (int o = 16; o > 0; o >>= 1) v += __shfl_xor_sync(0xffffffffu, v, o);
    return v;
}
__device__ __forceinline__ float wmax(float v) {
    #pragma unroll
    for (int o = 16; o > 0; o >>= 1) v = fmaxf(v, __shfl_xor_sync(0xffffffffu, v, o));
    return v;
}
__device__ __forceinline__ int wminI(int v) {
    #pragma unroll
    for (int o = 16; o > 0; o >>= 1) v = min(v, __shfl_xor_sync(0xffffffffu, v, o));
    return v;
}

// ---------------------------------------------------------------------------
// Fast atan2 (max err ~1e-6 rad), scalar.
// ---------------------------------------------------------------------------
__device__ __forceinline__ float fatan2f(float y, float x) {
    float ax = fabsf(x), ay = fabsf(y);
    float mx = fmaxf(ax, ay), mn = fminf(ax, ay);
    float a = __fdividef(mn, mx);
    if (mx == 0.0f) a = 0.0f;
    float s = a * a;
    float p =            -0.0040540580f;
    p = fmaf(p, s,        0.0218612288f);
    p = fmaf(p, s,       -0.0559098861f);
    p = fmaf(p, s,        0.0964200441f);
    p = fmaf(p, s,       -0.1390853351f);
    p = fmaf(p, s,        0.1994653599f);
    p = fmaf(p, s,       -0.3332985605f);
    p = fmaf(p, s,        0.9999993329f);
    float r = p * a;
    if (ay > ax)  r = 1.57079632679489662f - r;
    if (x < 0.0f) r = 3.14159265358979324f - r;
    return copysignf(r, y);
}

// ---------------------------------------------------------------------------
// Warp FFT-256 on complex-packed float2 state (re,im): 32 lanes x 8 points.
// Input: z[j] = value at time n = lane + 32*j. Output: reg j, lane l =
// Z[br3(j) + 8*br5(l)]. Butterfly adds/subs use f32x2 packed ops.
// ---------------------------------------------------------------------------
__device__ __forceinline__ void fft256w(float2 z[8],
                                        const float tw2r[8], const float tw2i[8],
                                        const float tw5r[4], const float tw5i[4],
                                        const float2 NEG1, int lane) {
    const float Cq = 0.70710678118654752440f;
    {   // stage d=4 with W8^j on the difference outputs
        float2 u, d;
        u = z[0]; d = F2SUB(z[0], z[4]); z[0] = f2add(u, z[4]);
        z[4] = d;                                               // W8^0 = 1
        u = z[1]; d = F2SUB(z[1], z[5]); z[1] = f2add(u, z[5]);
        z[5] = make_float2(Cq * (d.x + d.y), Cq * (d.y - d.x)); // W8^1
        u = z[2]; d = F2SUB(z[2], z[6]); z[2] = f2add(u, z[6]);
        z[6] = make_float2(d.y, -d.x);                          // W8^2 = -i
        u = z[3]; d = F2SUB(z[3], z[7]); z[3] = f2add(u, z[7]);
        z[7] = make_float2(Cq * (d.y - d.x), -Cq * (d.x + d.y));// W8^3
    }
    #pragma unroll
    for (int base = 0; base < 8; base += 4) {   // stage d=2
        float2 u, d;
        u = z[base];
        z[base]     = f2add(u, z[base + 2]);
        z[base + 2] = F2SUB(u, z[base + 2]);
        u = z[base + 1];
        d = F2SUB(z[base + 1], z[base + 3]);
        z[base + 1] = f2add(u, z[base + 3]);
        z[base + 3] = make_float2(d.y, -d.x);                   // * -i
    }
    #pragma unroll
    for (int base = 0; base < 8; base += 2) {   // stage d=1
        float2 u = z[base];
        z[base]     = f2add(u, z[base + 1]);
        z[base + 1] = F2SUB(u, z[base + 1]);
    }
    #pragma unroll
    for (int j = 1; j < 8; j++) {               // twiddle W256^(lane*br3(j))
        float xr = z[j].x, xi = z[j].y;
        z[j].x = xr * tw2r[j] - xi * tw2i[j];
        z[j].y = xr * tw2i[j] + xi * tw2r[j];
    }
    #pragma unroll
    for (int j = 0; j < 8; j++) {               // 32-pt DIF across lanes
        float2 v = z[j];
        #pragma unroll
        for (int s = 0; s < 4; s++) {
            int m = 16 >> s;
            float2 p;
            p.x = __shfl_xor_sync(0xffffffffu, v.x, m);
            p.y = __shfl_xor_sync(0xffffffffu, v.y, m);
            if (lane & m) {
                float2 d = F2SUB(p, v);
                v = make_float2(d.x * tw5r[s] - d.y * tw5i[s],
                                d.x * tw5i[s] + d.y * tw5r[s]);
            } else {
                v = f2add(v, p);
            }
        }
        float2 p;
        p.x = __shfl_xor_sync(0xffffffffu, v.x, 1);
        p.y = __shfl_xor_sync(0xffffffffu, v.y, 1);
        v = (lane & 1) ? F2SUB(p, v) : f2add(v, p);
        z[j] = v;
    }
}

// Padded smem index: conflict-free for bit-rev scatter, stride-8 mirrored
// reads, ordered scan reads, and natural-order reads.
__device__ __forceinline__ int spad(int t) { return t + (t >> 5); }

// ---------------------------------------------------------------------------
// Kernel 3: main — one WARP per (b,c) task; block = 4 warps, fixed c,
// each warp loops over 8 b values. Packed FFT: z = x + i*(x-mean)*win.
// Feature/dot section processes bins in (t, t+4) pairs with f32x2.
// 5 blocks/SM (20 warps) for latency hiding; reg cap 102.
// ---------------------------------------------------------------------------
__global__ void __launch_bounds__(128, 5) mainK(const float* __restrict__ W) {
    __shared__ float s_zr[4][264];
    __shared__ float s_zi[4][264];
    __shared__ float s_m [4][264];

    const int lane = threadIdx.x & 31;
    const int wrp  = threadIdx.x >> 5;
    const int c    = blockIdx.x;
    const int br3[8] = {0, 4, 2, 6, 1, 5, 3, 7};
    const int tbase = 8 * (int)(__brev((unsigned)lane) >> 27);

    const float2 NEG1 = make_float2(-1.0f, -1.0f);
    const float2 HALF = make_float2(0.5f, 0.5f);

    // Per-thread twiddles + Hann window (hoisted; reused across 8 tasks)
    float tw2r[8], tw2i[8], win[8];
    #pragma unroll
    for (int p = 0; p < 8; p++) {
        float sv, cv;
        sincosf(-6.28318530717958647692f * (float)(lane * br3[p]) * (1.0f / 256.0f), &sv, &cv);
        tw2r[p] = cv; tw2i[p] = sv;
        win[p] = 0.5f - 0.5f * cospif((float)(lane + 32 * p) * (1.0f / 128.0f));
    }
    float tw5r[4], tw5i[4];
    #pragma unroll
    for (int s = 0; s < 4; s++) {
        int m = 16 >> s;
        float sv, cv;
        sincosf(-3.14159265358979323846f * (float)(lane & (m - 1)) / (float)m, &sv, &cv);
        tw5r[s] = cv; tw5i[s] = sv;
    }

    float* szr = s_zr[wrp];
    float* szi = s_zi[wrp];
    float* smg = s_m [wrp];
    const float2* __restrict__ Wq = g_W4 + (c * 4) * 20 * 32 + lane;

    for (int it = 0; it < 8; ++it) {
        const int b = blockIdx.y * 32 + wrp * 8 + it;
        const float* __restrict__ xin = g_xT + (b * C_ + c) * T_;

        float xv[8];
        float ssum = 0.0f;
        #pragma unroll
        for (int j = 0; j < 8; j++) { xv[j] = xin[lane + 32 * j]; ssum += xv[j]; }
        const float mean = wsum(ssum) * (1.0f / 256.0f);

        // ---- packed FFT: real = x, imag = (x-mean)*win ----
        float2 z[8];
        #pragma unroll
        for (int j = 0; j < 8; j++) {
            z[j].x = xv[j];
            z[j].y = (xv[j] - mean) * win[j];
        }
        fft256w(z, tw2r, tw2i, tw5r, tw5i, NEG1, lane);

        // scatter Z to smem (needed for mirror unpack + Hilbert rebuild)
        #pragma unroll
        for (int j = 0; j < 8; j++) {
            int t = tbase + br3[j];
            szr[spad(t)] = z[j].x; szi[spad(t)] = z[j].y;
        }
        __syncwarp();

        // ---- unpack + per-bin features + fused dot, bin-PAIR packed ----
        float2 acc[K_], sb[K_];
        #pragma unroll
        for (int k = 0; k < K_; k++) { acc[k] = make_float2(0, 0); sb[k] = make_float2(0, 0); }
        float2 lsm2p = make_float2(0, 0), lm2p = make_float2(0, 0), lsfmp = make_float2(0, 0);
        float lpk = 0, lur = 0, lui = 0;
        #pragma unroll
        for (int jp = 0; jp < 4; jp++) {
            const int ja = 2 * jp, jb = 2 * jp + 1;
            const int ta = tbase + br3[ja];          // tb = ta + 4
            const int mta = (256 - ta) & 255;
            const int mtb = (252 - ta) & 255;
            float2 zr2 = make_float2(z[ja].x, z[jb].x);
            float2 zi2 = make_float2(z[ja].y, z[jb].y);
            float2 Mr2 = make_float2(szr[spad(mta)], szr[spad(mtb)]);
            float2 Mi2 = make_float2(szi[spad(mta)], szi[spad(mtb)]);
            float2 Xr2 = f2mul(f2add(zr2, Mr2), HALF);
            float2 Xi2 = f2mul(F2SUB(zi2, Mi2), HALF);
            float2 Wr2 = f2mul(f2add(zi2, Mi2), HALF);
            float2 Wi2 = f2mul(F2SUB(Mr2, zr2), HALF);
            float2 m22 = f2fma(Xi2, Xi2, f2mul(Xr2, Xr2));
            float2 rs2;
            rs2.x = (m22.x > 0.0f) ? rsqrtf(m22.x) : 0.0f;
            rs2.y = (m22.y > 0.0f) ? rsqrtf(m22.y) : 0.0f;
            float2 mg2 = f2mul(m22, rs2);
            smg[spad(ta)]     = mg2.x;
            smg[spad(ta + 4)] = mg2.y;
            float2 ph2 = make_float2(fatan2f(Xi2.x, Xr2.x), fatan2f(Xi2.y, Xr2.y));
            float2 ps2 = f2fma(Wi2, Wi2, f2mul(Wr2, Wr2));   // psd (scale in weights)
            float fqa = (ta < 128) ? (float)ta : (float)(ta - 256);
            float2 fq2 = make_float2(fqa, fqa + 4.0f);
            lsm2p = f2add(lsm2p, mg2);
            lm2p  = f2add(lm2p, m22);
            lsfmp = f2fma(mg2, fq2, lsfmp);
            lpk = fmaxf(lpk, fmaxf(mg2.x, mg2.y));
            float2 u2 = f2mul(Xr2, rs2), v2 = f2mul(Xi2, rs2);
            lur += (m22.x > 0.0f) ? u2.x : 1.0f;
            lur += (m22.y > 0.0f) ? u2.y : 1.0f;
            lui += v2.x + v2.y;
            const float2* wp = Wq + jp * (20 * 32);
            #pragma unroll
            for (int k = 0; k < K_; k++) {
                acc[k] = f2fma(ph2, wp[k * 32], acc[k]);
                acc[k] = f2fma(mg2, wp[(5 + k) * 32], acc[k]);
                acc[k] = f2fma(ps2, wp[(15 + k) * 32], acc[k]);
                sb[k]  = f2fma(mg2, wp[(10 + k) * 32], sb[k]);
            }
        }
        float sm  = wsum(lsm2p.x + lsm2p.y);
        float sm2 = wsum(lm2p.x + lm2p.y);
        float sfm = wsum(lsfmp.x + lsfmp.y);
        float pk  = wmax(lpk);
        float sur = wsum(lur);
        float sui = wsum(lui);

        __syncwarp();
        // ---- ordered cumsum of mag for rolloff/median (warp scan) ----
        float cs[8];
        float run = 0.0f;
        #pragma unroll
        for (int q = 0; q < 8; q++) {
            run += smg[spad(8 * lane + q)];
            cs[q] = run;
        }
        float incl = run;
        #pragma unroll
        for (int o = 1; o < 32; o <<= 1) {
            float vv = __shfl_up_sync(0xffffffffu, incl, o);
            if (lane >= o) incl += vv;
        }
        float excl  = incl - run;
        float total = __shfl_sync(0xffffffffu, incl, 31);
        float thr1 = 0.85f * total, thr2 = 0.5f * total;
        int cand1 = 1 << 30, cand2 = 1 << 30;
        #pragma unroll
        for (int q = 7; q >= 0; q--) {
            float v = excl + cs[q];
            if (v >= thr1) cand1 = 8 * lane + q;
            if (v >= thr2) cand2 = 8 * lane + q;
        }
        int rolli = wminI(cand1);
        int medi  = wminI(cand2);

        // ---- Hilbert FFT: input conj(X*h) in natural order from smem Z ----
        #pragma unroll
        for (int j = 0; j < 8; j++) {
            int n = lane + 32 * j;
            int mn_ = (256 - n) & 255;
            float Zr = szr[spad(n)],   Zi = szi[spad(n)];
            float Mr = szr[spad(mn_)], Mi = szi[spad(mn_)];
            float hh = (n == 0 || n == 128) ? 0.5f : ((n < 128) ? 1.0f : 0.0f);
            z[j].x =  (Zr + Mr) * hh;     // h*Xr
            z[j].y =  (Mi - Zi) * hh;     // -h*Xi
        }
        __syncwarp();   // smem reads done before next iteration's scatter
        fft256w(z, tw2r, tw2i, tw5r, tw5i, NEG1, lane);
        float2 la2p = make_float2(0, 0), la22p = make_float2(0, 0);
        #pragma unroll
        for (int jp = 0; jp < 4; jp++) {
            const int ja = 2 * jp, jb = 2 * jp + 1;
            float2 xr2 = make_float2(z[ja].x, z[jb].x);
            float2 xi2 = make_float2(z[ja].y, z[jb].y);
            float2 a2 = f2mul(f2fma(xi2, xi2, f2mul(xr2, xr2)),
                              make_float2(1.0f / 65536.0f, 1.0f / 65536.0f));
            float2 rs2;
            rs2.x = (a2.x > 0.0f) ? rsqrtf(a2.x) : 0.0f;
            rs2.y = (a2.y > 0.0f) ? rsqrtf(a2.y) : 0.0f;
            la2p  = f2add(la2p, f2mul(a2, rs2));
            la22p = f2add(la22p, a2);
        }
        float sa  = wsum(la2p.x + la2p.y);
        float sa2 = wsum(la22p.x + la22p.y);

        // ---- fold bicoh normalization, reduce accumulators ----
        float invn = rsqrtf(sm2);
        float accs[K_];
        #pragma unroll
        for (int k = 0; k < K_; k++) {
            float a = acc[k].x + acc[k].y + invn * (sb[k].x + sb[k].y);
            accs[k] = wsum(a);
        }

        if (lane == 0) {
            float pc   = sqrtf(sur * sur + sui * sui) * (1.0f / 256.0f);
            float cen  = sfm / sm;
            float rol  = (float)rolli;
            float avg  = sm * (1.0f / 256.0f);
            float medf = (medi < 128) ? (float)medi : (float)(medi - 256);
            float ma   = sa * (1.0f / 256.0f);
            float amp  = sqrtf(fmaxf(sa2 * (1.0f / 256.0f) - ma * ma, 0.0f));
            #pragma unroll
            for (int k = 0; k < K_; k++) {
                float v = accs[k]
                        + pc   * W[k * FC_ + 256 * C_ + c]
                        + cen  * W[k * FC_ + 769 * C_ + c]
                        + rol  * W[k * FC_ + 770 * C_ + c]
                        + pk   * W[k * FC_ + 771 * C_ + c]
                        + avg  * W[k * FC_ + 772 * C_ + c]
                        + medf * W[k * FC_ + 902 * C_ + c]
                        + amp  * W[k * FC_ + 903 * C_ + c];
                g_part[(c * B_ + b) * K_ + k] = v;
            }
        }
    }
}

// ---------------------------------------------------------------------------
// Kernel 4: reduce partials over channels + bias. One block per b.
// ---------------------------------------------------------------------------
__global__ void reduceK(const float* __restrict__ bias, float* __restrict__ out) {
    __shared__ float s[320];
    int b = blockIdx.x;
    int tid = threadIdx.x;                 // 320 threads
    int c = tid / 5, k = tid - 5 * c;
    s[tid] = g_part[(c * B_ + b) * K_ + k];
    __syncthreads();
    #pragma unroll
    for (int st = 160; st >= 5; st >>= 1) {
        if (tid < st) s[tid] += s[tid + st];
        __syncthreads();
    }
    if (tid < 5) out[b * K_ + tid] = s[tid] + bias[tid];
}

// ---------------------------------------------------------------------------
extern "C" void kernel_launch(void* const* d_in, const int* in_sizes, int n_in,
                              void* d_out, int out_size) {
    const float* x    = (const float*)d_in[0];   // (1024,256,64)
    // d_in[1] = x_mark_enc, unused
    const float* W    = (const float*)d_in[2];   // (5, 57856)
    const float* bias = (const float*)d_in[3];   // (5,)
    float* out = (float*)d_out;                  // (1024,5)

    buildW4<<<(C_ * 4 * 20 * 32 + 255) / 256, 256>>>(W);
    transposeX<<<dim3(T_ / 32, C_ / 32, B_), dim3(32, 8)>>>(x);
    mainK<<<dim3(C_, 32), 128>>>(W);
    reduceK<<<B_, 320>>>(bias, out);
}

// round 11
// speedup vs baseline: 1.1124x; 1.1124x over previous
#include <cuda_runtime.h>
#include <cuda_bf16.h>
#include <math.h>

// Fixed problem shapes
#define B_  1024
#define T_  256
#define C_  64
#define F_  904      // 3*256 + 129 + 7
#define K_  5
#define FC_ (F_ * C_)

// Scratch (device globals: allocation-free contract)
__device__ float  g_xT[B_ * C_ * T_];          // x transposed to [b][c][t]
__device__ float2 g_W4[C_ * 4 * 20 * 32];      // bin-PAIR weights (w_t, w_t4): [c][jp][q][lane]
__device__ float  g_part[C_ * B_ * K_];        // per-(c,b) partial dot products

// ---------------------------------------------------------------------------
// Packed f32x2 helpers (sm_100a).
// ---------------------------------------------------------------------------
__device__ __forceinline__ float2 f2add(float2 a, float2 b) {
    unsigned long long ua = *reinterpret_cast<unsigned long long*>(&a);
    unsigned long long ub = *reinterpret_cast<unsigned long long*>(&b);
    unsigned long long ud;
    asm("add.rn.f32x2 %0, %1, %2;" : "=l"(ud) : "l"(ua), "l"(ub));
    return *reinterpret_cast<float2*>(&ud);
}
__device__ __forceinline__ float2 f2mul(float2 a, float2 b) {
    unsigned long long ua = *reinterpret_cast<unsigned long long*>(&a);
    unsigned long long ub = *reinterpret_cast<unsigned long long*>(&b);
    unsigned long long ud;
    asm("mul.rn.f32x2 %0, %1, %2;" : "=l"(ud) : "l"(ua), "l"(ub));
    return *reinterpret_cast<float2*>(&ud);
}
__device__ __forceinline__ float2 f2fma(float2 a, float2 b, float2 c) {
    unsigned long long ua = *reinterpret_cast<unsigned long long*>(&a);
    unsigned long long ub = *reinterpret_cast<unsigned long long*>(&b);
    unsigned long long uc = *reinterpret_cast<unsigned long long*>(&c);
    unsigned long long ud;
    asm("fma.rn.f32x2 %0, %1, %2, %3;" : "=l"(ud) : "l"(ua), "l"(ub), "l"(uc));
    return *reinterpret_cast<float2*>(&ud);
}
// exact a-b via fma(b, (-1,-1), a)
#define F2SUB(a, b) f2fma((b), NEG1, (a))

// ---------------------------------------------------------------------------
// Weight row value for feature row r, bin t, class k, channel c.
// ---------------------------------------------------------------------------
__device__ __forceinline__ float wval(const float* __restrict__ W,
                                      int r, int t, int k, int c) {
    float w = 0.0f;
    if (r == 0)      w = W[k * FC_ + t * C_ + c];
    else if (r == 1) w = W[k * FC_ + (257 + t) * C_ + c];
    else if (r == 2) w = W[k * FC_ + (513 + t) * C_ + c];
    else {
        const float sc = 1.0f / 24576.0f;   // 1/(fs*sum(win^2))
        if (t == 0)        w = W[k * FC_ + 773 * C_ + c] * sc;
        else if (t < 128)  w = W[k * FC_ + (773 + t) * C_ + c] * (2.0f * sc);
        else if (t == 128) w = W[k * FC_ + (773 + 128) * C_ + c] * sc;
    }
    return w;
}

// ---------------------------------------------------------------------------
// Kernel 1: build bin-pair weight table. Registers j=2*jp, 2*jp+1 hold bins
// t and t+4 (br3 pairs). Element = (w(t), w(t+4)).
// Layout index = ((c*4+jp)*20+q)*32 + lane.
// ---------------------------------------------------------------------------
__global__ void buildW4(const float* __restrict__ W) {
    int idx = blockIdx.x * blockDim.x + threadIdx.x;
    const int N = C_ * 4 * 20 * 32;
    if (idx >= N) return;
    int l  = idx & 31;
    int r1 = idx >> 5;
    int q  = r1 % 20; r1 /= 20;
    int jp = r1 & 3;
    int c  = r1 >> 2;
    const int br3[8] = {0, 4, 2, 6, 1, 5, 3, 7};
    int t = br3[2 * jp] + 8 * (int)(__brev((unsigned)l) >> 27);
    int r = q / 5, k = q - 5 * r;
    g_W4[idx] = make_float2(wval(W, r, t, k, c), wval(W, r, t + 4, k, c));
}

// ---------------------------------------------------------------------------
// Kernel 2: transpose x (B,T,C) -> xT (B,C,T)
// ---------------------------------------------------------------------------
__global__ void transposeX(const float* __restrict__ x) {
    __shared__ float tile[32][33];
    int b  = blockIdx.z;
    int t0 = blockIdx.x * 32;
    int c0 = blockIdx.y * 32;
    int tx = threadIdx.x, ty = threadIdx.y;   // (32,8)
    #pragma unroll
    for (int i = 0; i < 32; i += 8) {
        int t = t0 + ty + i, c = c0 + tx;
        tile[ty + i][tx] = x[(b * T_ + t) * C_ + c];
    }
    __syncthreads();
    #pragma unroll
    for (int i = 0; i < 32; i += 8) {
        int c = c0 + ty + i, t = t0 + tx;
        g_xT[(b * C_ + c) * T_ + t] = tile[tx][ty + i];
    }
}

// ---------------------------------------------------------------------------
// Warp reduction helpers
// ---------------------------------------------------------------------------
__device__ __forceinline__ float wsum(float v) {
    #pragma unroll
    for (int o = 16; o > 0; o >>= 1) v += __shfl_xor_sync(0xffffffffu, v, o);
    return v;
}
__device__ __forceinline__ float wmax(float v) {
    #pragma unroll
    for (int o = 16; o > 0; o >>= 1) v = fmaxf(v, __shfl_xor_sync(0xffffffffu, v, o));
    return v;
}
__device__ __forceinline__ int wminI(int v) {
    #pragma unroll
    for (int o = 16; o > 0; o >>= 1) v = min(v, __shfl_xor_sync(0xffffffffu, v, o));
    return v;
}

// ---------------------------------------------------------------------------
// Fast atan2 (max err ~1e-6 rad), scalar.
// ---------------------------------------------------------------------------
__device__ __forceinline__ float fatan2f(float y, float x) {
    float ax = fabsf(x), ay = fabsf(y);
    float mx = fmaxf(ax, ay), mn = fminf(ax, ay);
    float a = __fdividef(mn, mx);
    if (mx == 0.0f) a = 0.0f;
    float s = a * a;
    float p =            -0.0040540580f;
    p = fmaf(p, s,        0.0218612288f);
    p = fmaf(p, s,       -0.0559098861f);
    p = fmaf(p, s,        0.0964200441f);
    p = fmaf(p, s,       -0.1390853351f);
    p = fmaf(p, s,        0.1994653599f);
    p = fmaf(p, s,       -0.3332985605f);
    p = fmaf(p, s,        0.9999993329f);
    float r = p * a;
    if (ay > ax)  r = 1.57079632679489662f - r;
    if (x < 0.0f) r = 3.14159265358979324f - r;
    return copysignf(r, y);
}

// ---------------------------------------------------------------------------
// Warp FFT-256 on complex-packed float2 state (re,im): 32 lanes x 8 points.
// Input: z[j] = value at time n = lane + 32*j. Output: reg j, lane l =
// Z[br3(j) + 8*br5(l)]. Radix-stage twiddles come from a block-shared smem
// table stw2[j*32+lane] (frees 16 regs/thread); lane-stage tw5 in registers.
// ---------------------------------------------------------------------------
__device__ __forceinline__ void fft256w(float2 z[8],
                                        const float2* __restrict__ stw2,
                                        const float tw5r[4], const float tw5i[4],
                                        const float2 NEG1, int lane) {
    const float Cq = 0.70710678118654752440f;
    {   // stage d=4 with W8^j on the difference outputs
        float2 u, d;
        u = z[0]; d = F2SUB(z[0], z[4]); z[0] = f2add(u, z[4]);
        z[4] = d;                                               // W8^0 = 1
        u = z[1]; d = F2SUB(z[1], z[5]); z[1] = f2add(u, z[5]);
        z[5] = make_float2(Cq * (d.x + d.y), Cq * (d.y - d.x)); // W8^1
        u = z[2]; d = F2SUB(z[2], z[6]); z[2] = f2add(u, z[6]);
        z[6] = make_float2(d.y, -d.x);                          // W8^2 = -i
        u = z[3]; d = F2SUB(z[3], z[7]); z[3] = f2add(u, z[7]);
        z[7] = make_float2(Cq * (d.y - d.x), -Cq * (d.x + d.y));// W8^3
    }
    #pragma unroll
    for (int base = 0; base < 8; base += 4) {   // stage d=2
        float2 u, d;
        u = z[base];
        z[base]     = f2add(u, z[base + 2]);
        z[base + 2] = F2SUB(u, z[base + 2]);
        u = z[base + 1];
        d = F2SUB(z[base + 1], z[base + 3]);
        z[base + 1] = f2add(u, z[base + 3]);
        z[base + 3] = make_float2(d.y, -d.x);                   // * -i
    }
    #pragma unroll
    for (int base = 0; base < 8; base += 2) {   // stage d=1
        float2 u = z[base];
        z[base]     = f2add(u, z[base + 1]);
        z[base + 1] = F2SUB(u, z[base + 1]);
    }
    #pragma unroll
    for (int j = 1; j < 8; j++) {               // twiddle W256^(lane*br3(j))
        float2 w = stw2[j * 32 + lane];
        float xr = z[j].x, xi = z[j].y;
        z[j].x = xr * w.x - xi * w.y;
        z[j].y = xr * w.y + xi * w.x;
    }
    #pragma unroll
    for (int j = 0; j < 8; j++) {               // 32-pt DIF across lanes
        float2 v = z[j];
        #pragma unroll
        for (int s = 0; s < 4; s++) {
            int m = 16 >> s;
            float2 p;
            p.x = __shfl_xor_sync(0xffffffffu, v.x, m);
            p.y = __shfl_xor_sync(0xffffffffu, v.y, m);
            if (lane & m) {
                float2 d = F2SUB(p, v);
                v = make_float2(d.x * tw5r[s] - d.y * tw5i[s],
                                d.x * tw5i[s] + d.y * tw5r[s]);
            } else {
                v = f2add(v, p);
            }
        }
        float2 p;
        p.x = __shfl_xor_sync(0xffffffffu, v.x, 1);
        p.y = __shfl_xor_sync(0xffffffffu, v.y, 1);
        v = (lane & 1) ? F2SUB(p, v) : f2add(v, p);
        z[j] = v;
    }
}

// Padded smem index: conflict-free for bit-rev scatter, stride-8 mirrored
// reads, ordered scan reads, and natural-order reads.
__device__ __forceinline__ int spad(int t) { return t + (t >> 5); }

// ---------------------------------------------------------------------------
// Kernel 3: main — one WARP per (b,c) task; block = 4 warps, fixed c,
// each warp loops over 8 b values. Packed FFT: z = x + i*(x-mean)*win.
// Feature/dot section processes bins in (t, t+4) pairs with f32x2.
// Constant tables (twiddle, window) in block-shared smem to cut registers;
// 5 blocks/SM (20 warps) for latency hiding.
// ---------------------------------------------------------------------------
__global__ void __launch_bounds__(128, 5) mainK(const float* __restrict__ W) {
    __shared__ float  s_zr[4][264];
    __shared__ float  s_zi[4][264];
    __shared__ float  s_m [4][264];
    __shared__ float2 s_tw2[256];    // (cos,sin) of W256^(lane*br3(j)), idx j*32+lane
    __shared__ float  s_win[256];    // Hann at n = lane+32*j, idx j*32+lane

    const int lane = threadIdx.x & 31;
    const int wrp  = threadIdx.x >> 5;
    const int c    = blockIdx.x;
    const int br3[8] = {0, 4, 2, 6, 1, 5, 3, 7};
    const int tbase = 8 * (int)(__brev((unsigned)lane) >> 27);

    const float2 NEG1 = make_float2(-1.0f, -1.0f);
    const float2 HALF = make_float2(0.5f, 0.5f);

    // Init shared constant tables (128 threads cover 256 entries)
    for (int idx = threadIdx.x; idx < 256; idx += 128) {
        int jj = idx >> 5, ll = idx & 31;
        float sv, cv;
        sincosf(-6.28318530717958647692f * (float)(ll * br3[jj]) * (1.0f / 256.0f), &sv, &cv);
        s_tw2[idx] = make_float2(cv, sv);
        s_win[idx] = 0.5f - 0.5f * cospif((float)(ll + 32 * jj) * (1.0f / 128.0f));
    }

    // Lane-stage twiddles stay in registers (8 regs, on the shfl chain)
    float tw5r[4], tw5i[4];
    #pragma unroll
    for (int s = 0; s < 4; s++) {
        int m = 16 >> s;
        float sv, cv;
        sincosf(-3.14159265358979323846f * (float)(lane & (m - 1)) / (float)m, &sv, &cv);
        tw5r[s] = cv; tw5i[s] = sv;
    }
    __syncthreads();

    float* szr = s_zr[wrp];
    float* szi = s_zi[wrp];
    float* smg = s_m [wrp];
    const float2* __restrict__ Wq = g_W4 + (c * 4) * 20 * 32 + lane;

    for (int it = 0; it < 8; ++it) {
        const int b = blockIdx.y * 32 + wrp * 8 + it;
        const float* __restrict__ xin = g_xT + (b * C_ + c) * T_;

        float xv[8];
        float ssum = 0.0f;
        #pragma unroll
        for (int j = 0; j < 8; j++) { xv[j] = xin[lane + 32 * j]; ssum += xv[j]; }
        const float mean = wsum(ssum) * (1.0f / 256.0f);

        // ---- packed FFT: real = x, imag = (x-mean)*win ----
        float2 z[8];
        #pragma unroll
        for (int j = 0; j < 8; j++) {
            z[j].x = xv[j];
            z[j].y = (xv[j] - mean) * s_win[j * 32 + lane];
        }
        fft256w(z, s_tw2, tw5r, tw5i, NEG1, lane);

        // scatter Z to smem (needed for mirror unpack + Hilbert rebuild)
        #pragma unroll
        for (int j = 0; j < 8; j++) {
            int t = tbase + br3[j];
            szr[spad(t)] = z[j].x; szi[spad(t)] = z[j].y;
        }
        __syncwarp();

        // ---- unpack + per-bin features + fused dot, bin-PAIR packed ----
        float2 acc[K_], sb[K_];
        #pragma unroll
        for (int k = 0; k < K_; k++) { acc[k] = make_float2(0, 0); sb[k] = make_float2(0, 0); }
        float2 lsm2p = make_float2(0, 0), lm2p = make_float2(0, 0), lsfmp = make_float2(0, 0);
        float lpk = 0, lur = 0, lui = 0;
        #pragma unroll
        for (int jp = 0; jp < 4; jp++) {
            const int ja = 2 * jp, jb = 2 * jp + 1;
            const int ta = tbase + br3[ja];          // tb = ta + 4
            const int mta = (256 - ta) & 255;
            const int mtb = (252 - ta) & 255;
            float2 zr2 = make_float2(z[ja].x, z[jb].x);
            float2 zi2 = make_float2(z[ja].y, z[jb].y);
            float2 Mr2 = make_float2(szr[spad(mta)], szr[spad(mtb)]);
            float2 Mi2 = make_float2(szi[spad(mta)], szi[spad(mtb)]);
            float2 Xr2 = f2mul(f2add(zr2, Mr2), HALF);
            float2 Xi2 = f2mul(F2SUB(zi2, Mi2), HALF);
            float2 Wr2 = f2mul(f2add(zi2, Mi2), HALF);
            float2 Wi2 = f2mul(F2SUB(Mr2, zr2), HALF);
            float2 m22 = f2fma(Xi2, Xi2, f2mul(Xr2, Xr2));
            float2 rs2;
            rs2.x = (m22.x > 0.0f) ? rsqrtf(m22.x) : 0.0f;
            rs2.y = (m22.y > 0.0f) ? rsqrtf(m22.y) : 0.0f;
            float2 mg2 = f2mul(m22, rs2);
            smg[spad(ta)]     = mg2.x;
            smg[spad(ta + 4)] = mg2.y;
            float2 ph2 = make_float2(fatan2f(Xi2.x, Xr2.x), fatan2f(Xi2.y, Xr2.y));
            float2 ps2 = f2fma(Wi2, Wi2, f2mul(Wr2, Wr2));   // psd (scale in weights)
            float fqa = (ta < 128) ? (float)ta : (float)(ta - 256);
            float2 fq2 = make_float2(fqa, fqa + 4.0f);
            lsm2p = f2add(lsm2p, mg2);
            lm2p  = f2add(lm2p, m22);
            lsfmp = f2fma(mg2, fq2, lsfmp);
            lpk = fmaxf(lpk, fmaxf(mg2.x, mg2.y));
            float2 u2 = f2mul(Xr2, rs2), v2 = f2mul(Xi2, rs2);
            lur += (m22.x > 0.0f) ? u2.x : 1.0f;
            lur += (m22.y > 0.0f) ? u2.y : 1.0f;
            lui += v2.x + v2.y;
            const float2* wp = Wq + jp * (20 * 32);
            #pragma unroll
            for (int k = 0; k < K_; k++) {
                acc[k] = f2fma(ph2, wp[k * 32], acc[k]);
                acc[k] = f2fma(mg2, wp[(5 + k) * 32], acc[k]);
                acc[k] = f2fma(ps2, wp[(15 + k) * 32], acc[k]);
                sb[k]  = f2fma(mg2, wp[(10 + k) * 32], sb[k]);
            }
        }
        float sm  = wsum(lsm2p.x + lsm2p.y);
        float sm2 = wsum(lm2p.x + lm2p.y);
        float sfm = wsum(lsfmp.x + lsfmp.y);
        float pk  = wmax(lpk);
        float sur = wsum(lur);
        float sui = wsum(lui);

        __syncwarp();
        // ---- ordered cumsum of mag for rolloff/median (warp scan) ----
        float cs[8];
        float run = 0.0f;
        #pragma unroll
        for (int q = 0; q < 8; q++) {
            run += smg[spad(8 * lane + q)];
            cs[q] = run;
        }
        float incl = run;
        #pragma unroll
        for (int o = 1; o < 32; o <<= 1) {
            float vv = __shfl_up_sync(0xffffffffu, incl, o);
            if (lane >= o) incl += vv;
        }
        float excl  = incl - run;
        float total = __shfl_sync(0xffffffffu, incl, 31);
        float thr1 = 0.85f * total, thr2 = 0.5f * total;
        int cand1 = 1 << 30, cand2 = 1 << 30;
        #pragma unroll
        for (int q = 7; q >= 0; q--) {
            float v = excl + cs[q];
            if (v >= thr1) cand1 = 8 * lane + q;
            if (v >= thr2) cand2 = 8 * lane + q;
        }
        int rolli = wminI(cand1);
        int medi  = wminI(cand2);

        // ---- Hilbert FFT: input conj(X*h) in natural order from smem Z ----
        #pragma unroll
        for (int j = 0; j < 8; j++) {
            int n = lane + 32 * j;
            int mn_ = (256 - n) & 255;
            float Zr = szr[spad(n)],   Zi = szi[spad(n)];
            float Mr = szr[spad(mn_)], Mi = szi[spad(mn_)];
            float hh = (n == 0 || n == 128) ? 0.5f : ((n < 128) ? 1.0f : 0.0f);
            z[j].x =  (Zr + Mr) * hh;     // h*Xr
            z[j].y =  (Mi - Zi) * hh;     // -h*Xi
        }
        __syncwarp();   // smem reads done before next iteration's scatter
        fft256w(z, s_tw2, tw5r, tw5i, NEG1, lane);
        float2 la2p = make_float2(0, 0), la22p = make_float2(0, 0);
        #pragma unroll
        for (int jp = 0; jp < 4; jp++) {
            const int ja = 2 * jp, jb = 2 * jp + 1;
            float2 xr2 = make_float2(z[ja].x, z[jb].x);
            float2 xi2 = make_float2(z[ja].y, z[jb].y);
            float2 a2 = f2mul(f2fma(xi2, xi2, f2mul(xr2, xr2)),
                              make_float2(1.0f / 65536.0f, 1.0f / 65536.0f));
            float2 rs2;
            rs2.x = (a2.x > 0.0f) ? rsqrtf(a2.x) : 0.0f;
            rs2.y = (a2.y > 0.0f) ? rsqrtf(a2.y) : 0.0f;
            la2p  = f2add(la2p, f2mul(a2, rs2));
            la22p = f2add(la22p, a2);
        }
        float sa  = wsum(la2p.x + la2p.y);
        float sa2 = wsum(la22p.x + la22p.y);

        // ---- fold bicoh normalization, reduce accumulators ----
        float invn = rsqrtf(sm2);
        float accs[K_];
        #pragma unroll
        for (int k = 0; k < K_; k++) {
            float a = acc[k].x + acc[k].y + invn * (sb[k].x + sb[k].y);
            accs[k] = wsum(a);
        }

        if (lane == 0) {
            float pc   = sqrtf(sur * sur + sui * sui) * (1.0f / 256.0f);
            float cen  = sfm / sm;
            float rol  = (float)rolli;
            float avg  = sm * (1.0f / 256.0f);
            float medf = (medi < 128) ? (float)medi : (float)(medi - 256);
            float ma   = sa * (1.0f / 256.0f);
            float amp  = sqrtf(fmaxf(sa2 * (1.0f / 256.0f) - ma * ma, 0.0f));
            #pragma unroll
            for (int k = 0; k < K_; k++) {
                float v = accs[k]
                        + pc   * W[k * FC_ + 256 * C_ + c]
                        + cen  * W[k * FC_ + 769 * C_ + c]
                        + rol  * W[k * FC_ + 770 * C_ + c]
                        + pk   * W[k * FC_ + 771 * C_ + c]
                        + avg  * W[k * FC_ + 772 * C_ + c]
                        + medf * W[k * FC_ + 902 * C_ + c]
                        + amp  * W[k * FC_ + 903 * C_ + c];
                g_part[(c * B_ + b) * K_ + k] = v;
            }
        }
    }
}

// ---------------------------------------------------------------------------
// Kernel 4: reduce partials over channels + bias. One block per b.
// ---------------------------------------------------------------------------
__global__ void reduceK(const float* __restrict__ bias, float* __restrict__ out) {
    __shared__ float s[320];
    int b = blockIdx.x;
    int tid = threadIdx.x;                 // 320 threads
    int c = tid / 5, k = tid - 5 * c;
    s[tid] = g_part[(c * B_ + b) * K_ + k];
    __syncthreads();
    #pragma unroll
    for (int st = 160; st >= 5; st >>= 1) {
        if (tid < st) s[tid] += s[tid + st];
        __syncthreads();
    }
    if (tid < 5) out[b * K_ + tid] = s[tid] + bias[tid];
}

// ---------------------------------------------------------------------------
extern "C" void kernel_launch(void* const* d_in, const int* in_sizes, int n_in,
                              void* d_out, int out_size) {
    const float* x    = (const float*)d_in[0];   // (1024,256,64)
    // d_in[1] = x_mark_enc, unused
    const float* W    = (const float*)d_in[2];   // (5, 57856)
    const float* bias = (const float*)d_in[3];   // (5,)
    float* out = (float*)d_out;                  // (1024,5)

    buildW4<<<(C_ * 4 * 20 * 32 + 255) / 256, 256>>>(W);
    transposeX<<<dim3(T_ / 32, C_ / 32, B_), dim3(32, 8)>>>(x);
    mainK<<<dim3(C_, 32), 128>>>(W);
    reduceK<<<B_, 320>>>(bias, out);
}